// round 15
// baseline (speedup 1.0000x reference)
#include <cuda_runtime.h>

// AnchorLoss: sum over masked pairs of 1 - exp(-||(e_i+a_i)-(e_j+a_j)||^2 / 10)
// B=8, N=2048, D=2. Mandatory traffic: the 134MB int32 mask, read once.
//
// R15 (from R14; DRAM pinned at 71% across 3 structurally different kernels):
//  - 256-col slabs: warp reads 1KB CONTIGUOUS per mask row (2xLDG.128) ->
//    2x DRAM page sequential locality (attacks the suspected row-buffer miss
//    plateau). 8 point-consts/lane (two 4-point groups), chunk-granular ring.
//  - memset-free epilogue: self-resetting __device__ accumulator + done
//    counter; last block writes *out and re-zeros state (graph loses both
//    memset nodes, ~2us of bench-side overhead).
// Core math unchanged: exponent = w_r + w_c + 2u_r*u_c + 2v_r*v_c;
// pair = 2xFFMA+MUFU+ISETP+@P FADD; 2^(w_r) factored per row; row consts via
// SHFL (lanes 0..7); count-minus-sum accumulation.

#define BATCH    8
#define NPTS     2048
#define THREADS  128
#define NWARPS   4
#define ROWS_IT  32                      // rows per item/block
#define ROWS_PW  8                       // rows per warp
#define RING     8                       // int4-chunk ring (2 chunks per row)
#define GRID     (BATCH * 8 * 64)        // 4096: 8 slabs x 64 row-groups

__device__ float    g_acc;               // zero-initialized; self-resetting
__device__ unsigned g_done;

__global__ void __launch_bounds__(THREADS, 6) anchor_loss_kernel(
    const float* __restrict__ emb,
    const float* __restrict__ abscoords,
    const int*   __restrict__ mask,
    float*       __restrict__ out)
{
    __shared__ float wsum[NWARPS];

    const int warp = threadIdx.x >> 5;
    const int lane = threadIdx.x & 31;
    const float S = 0.37982354f;         // sqrt(log2(e)/10)

    // 4096 blocks = 8 batches * 8 slabs(256 cols) * 64 row-groups
    const int b   = blockIdx.x >> 9;             // 512 items per batch
    const int rem = blockIdx.x & 511;
    const int j0  = (rem >> 6) * 256;            // column slab base
    const int i0  = (rem & 63) * ROWS_IT;        // row-group base

    const float2* e2 = (const float2*)emb       + (size_t)b * NPTS;
    const float2* a2 = (const float2*)abscoords + (size_t)b * NPTS;

    // ---- FIRST: deep mask prefetch. chunk c = row (c>>1), half (c&1);
    //      addr = mrow + 512*(c>>1) + 32*(c&1). 8 chunks = 4 rows in flight.
    const int iA = i0 + warp * ROWS_PW;
    const int4* mrow = reinterpret_cast<const int4*>(
        mask + ((size_t)b * NPTS + iA) * NPTS + j0) + lane;

    int4 mb[RING];
    #pragma unroll
    for (int c = 0; c < RING; c++)
        mb[c] = __ldcs(mrow + 512 * (c >> 1) + 32 * (c & 1));

    // ---- lane's 8 slab-point constants: group A (cols j0+4l..) and
    //      group B (cols j0+128+4l..) — L2 hits ----
    float uA[4], vA[4], wA[4], uB[4], vB[4], wB[4];
    {
        const float4* ee = reinterpret_cast<const float4*>(e2 + j0);
        const float4* aa = reinterpret_cast<const float4*>(a2 + j0);
        float4 ex0 = __ldg(ee + 2 * lane);
        float4 ex1 = __ldg(ee + 2 * lane + 1);
        float4 ax0 = __ldg(aa + 2 * lane);
        float4 ax1 = __ldg(aa + 2 * lane + 1);
        uA[0] = (ex0.x + ax0.x) * S;  vA[0] = (ex0.y + ax0.y) * S;
        uA[1] = (ex0.z + ax0.z) * S;  vA[1] = (ex0.w + ax0.w) * S;
        uA[2] = (ex1.x + ax1.x) * S;  vA[2] = (ex1.y + ax1.y) * S;
        uA[3] = (ex1.z + ax1.z) * S;  vA[3] = (ex1.w + ax1.w) * S;
        ex0 = __ldg(ee + 64 + 2 * lane);         // +128 points = +64 float4
        ex1 = __ldg(ee + 64 + 2 * lane + 1);
        ax0 = __ldg(aa + 64 + 2 * lane);
        ax1 = __ldg(aa + 64 + 2 * lane + 1);
        uB[0] = (ex0.x + ax0.x) * S;  vB[0] = (ex0.y + ax0.y) * S;
        uB[1] = (ex0.z + ax0.z) * S;  vB[1] = (ex0.w + ax0.w) * S;
        uB[2] = (ex1.x + ax1.x) * S;  vB[2] = (ex1.y + ax1.y) * S;
        uB[3] = (ex1.z + ax1.z) * S;  vB[3] = (ex1.w + ax1.w) * S;
        #pragma unroll
        for (int k = 0; k < 4; k++) {
            wA[k] = -fmaf(uA[k], uA[k], vA[k] * vA[k]);
            wB[k] = -fmaf(uB[k], uB[k], vB[k] * vB[k]);
        }
    }

    // ---- warp's 8 row constants: lanes 0..7 own one row each ----
    float ru2, rv2, rew;
    {
        const int rl = iA + (lane & (ROWS_PW - 1));
        float2 er = __ldg(e2 + rl);
        float2 ar = __ldg(a2 + rl);
        float u = (er.x + ar.x) * S;
        float v = (er.y + ar.y) * S;
        ru2 = u + u;
        rv2 = v + v;
        float w = -fmaf(u, u, v * v);
        asm("ex2.approx.ftz.f32 %0, %1;" : "=f"(rew) : "f"(w));   // 2^(w_r)
    }

    float es  = 0.0f;
    int   cnt = 0;

    #pragma unroll
    for (int r = 0; r < ROWS_PW; r++) {
        const int4 m0 = mb[(2 * r)     & (RING - 1)];
        const int4 m1 = mb[(2 * r + 1) & (RING - 1)];
        // statically-guarded refill: row r+4's two chunks (no wasted loads)
        if (r + 4 < ROWS_PW) {
            mb[(2 * r)     & (RING - 1)] = __ldcs(mrow + 512 * (r + 4));
            mb[(2 * r + 1) & (RING - 1)] = __ldcs(mrow + 512 * (r + 4) + 32);
        }

        const float u2r = __shfl_sync(0xffffffffu, ru2, r);
        const float v2r = __shfl_sync(0xffffffffu, rv2, r);
        const float ewr = __shfl_sync(0xffffffffu, rew, r);

        float racc = 0.0f;
        float tt, ev;

        tt = fmaf(u2r, uA[0], wA[0]);
        tt = fmaf(v2r, vA[0], tt);
        asm("ex2.approx.ftz.f32 %0, %1;" : "=f"(ev) : "f"(tt));
        if (m0.x) racc += ev;

        tt = fmaf(u2r, uA[1], wA[1]);
        tt = fmaf(v2r, vA[1], tt);
        asm("ex2.approx.ftz.f32 %0, %1;" : "=f"(ev) : "f"(tt));
        if (m0.y) racc += ev;

        tt = fmaf(u2r, uA[2], wA[2]);
        tt = fmaf(v2r, vA[2], tt);
        asm("ex2.approx.ftz.f32 %0, %1;" : "=f"(ev) : "f"(tt));
        if (m0.z) racc += ev;

        tt = fmaf(u2r, uA[3], wA[3]);
        tt = fmaf(v2r, vA[3], tt);
        asm("ex2.approx.ftz.f32 %0, %1;" : "=f"(ev) : "f"(tt));
        if (m0.w) racc += ev;

        tt = fmaf(u2r, uB[0], wB[0]);
        tt = fmaf(v2r, vB[0], tt);
        asm("ex2.approx.ftz.f32 %0, %1;" : "=f"(ev) : "f"(tt));
        if (m1.x) racc += ev;

        tt = fmaf(u2r, uB[1], wB[1]);
        tt = fmaf(v2r, vB[1], tt);
        asm("ex2.approx.ftz.f32 %0, %1;" : "=f"(ev) : "f"(tt));
        if (m1.y) racc += ev;

        tt = fmaf(u2r, uB[2], wB[2]);
        tt = fmaf(v2r, vB[2], tt);
        asm("ex2.approx.ftz.f32 %0, %1;" : "=f"(ev) : "f"(tt));
        if (m1.z) racc += ev;

        tt = fmaf(u2r, uB[3], wB[3]);
        tt = fmaf(v2r, vB[3], tt);
        asm("ex2.approx.ftz.f32 %0, %1;" : "=f"(ev) : "f"(tt));
        if (m1.w) racc += ev;

        es = fmaf(racc, ewr, es);                     // row partial * 2^(w_r)
        cnt += (m0.x + m0.y) + (m0.z + m0.w)
             + (m1.x + m1.y) + (m1.z + m1.w);         // mask values are 0/1
    }

    float acc = (float)cnt - es;                      // masked sum of (1 - e)

    #pragma unroll
    for (int off = 16; off; off >>= 1)
        acc += __shfl_xor_sync(0xffffffffu, acc, off);
    if (lane == 0) wsum[warp] = acc;
    __syncthreads();

    // ---- memset-free epilogue: self-resetting global accumulator ----
    if (threadIdx.x == 0) {
        float s = 0.0f;
        #pragma unroll
        for (int w = 0; w < NWARPS; w++) s += wsum[w];
        atomicAdd(&g_acc, s);
        __threadfence();
        unsigned d = atomicAdd(&g_done, 1u);
        if (d == GRID - 1) {                 // last block: publish + reset
            __threadfence();
            float tot = *((volatile float*)&g_acc);
            *out = tot;
            *((volatile float*)&g_acc)     = 0.0f;
            *((volatile unsigned*)&g_done) = 0u;
            __threadfence();
        }
    }
}

extern "C" void kernel_launch(void* const* d_in, const int* in_sizes, int n_in,
                              void* d_out, int out_size)
{
    const float* emb  = (const float*)d_in[0];
    const float* absc = (const float*)d_in[1];
    const int*   mask = (const int*)d_in[2];
    float*       out  = (float*)d_out;

    anchor_loss_kernel<<<GRID, THREADS>>>(emb, absc, mask, out);
}